// round 16
// baseline (speedup 1.0000x reference)
#include <cuda_runtime.h>
#include <cstddef>

// ProdLayer forward: element_mars[nids] = node_mars[cids].sum(axis=1)
//   d_in[0] node_mars     float32  [N_SRC, 128]
//   d_in[1] element_mars  float32  [N_PROD+1, 128]
//   d_in[2] nids          int32    [N_PROD]
//   d_in[3] cids          int32    [N_PROD, 4]
// Output: float32 [N_PROD+1, 128]
//
// R16: last untested knob in the store-policy family. __stwt
// (st.global.wt, write-through) instead of __stcs on the output: __stcs
// lines are evict-first but still write-back ALLOCATED, so at 6.8 TB/s a
// standing population of dirty output lines occupies L2 from fill to
// writeback drain. Write-through collapses that dirty-residency window,
// freeing line slots for the randomly re-referenced node_mars rows
// (same mechanism family as R2's -2% __stcs win).
//
// Everything else is the 14-round converged form: flat launch,
// warp-per-product, float4 lanes, 4 coalesced LDG.128 gathers (__ldg),
// __ldcs index reads. Traffic irreducibly ~1.13 GB at 86% of spec HBM;
// falsified alternatives documented in R3-R15 (tiling, policies, L1
// bypass, LDG.256, persistent grids, MLP/CTA-size/order variants).

static constexpr int B_F4 = 32;  // 128 floats / 4 per row

__global__ void __launch_bounds__(256) prodlayer_kernel(
    const float4* __restrict__ node_mars,
    const float4* __restrict__ element_mars,
    const int*    __restrict__ nids,
    const int4*   __restrict__ cids,
    float4*       __restrict__ out,
    int n_prod)
{
    const int gwarp = (int)((blockIdx.x * (unsigned)blockDim.x + threadIdx.x) >> 5);
    const int lane  = threadIdx.x & 31;

    if (gwarp < n_prod) {
        const int4 c = __ldcs(&cids[gwarp]);      // streaming index read

        const float4 a = __ldg(&node_mars[(size_t)c.x * B_F4 + lane]);
        const float4 b = __ldg(&node_mars[(size_t)c.y * B_F4 + lane]);
        const float4 d = __ldg(&node_mars[(size_t)c.z * B_F4 + lane]);
        const float4 e = __ldg(&node_mars[(size_t)c.w * B_F4 + lane]);

        float4 s;
        s.x = (a.x + b.x) + (d.x + e.x);
        s.y = (a.y + b.y) + (d.y + e.y);
        s.z = (a.z + b.z) + (d.z + e.z);
        s.w = (a.w + b.w) + (d.w + e.w);

        const int o = __ldcs(&nids[gwarp]);
        __stwt(&out[(size_t)o * B_F4 + lane], s);  // write-through store
    } else if (gwarp == n_prod) {
        // Reserved row 0: out row 0 = element_mars row 0 (d_out is poisoned
        // to 0xAA before timing, so row 0 must be written explicitly).
        __stwt(&out[lane], __ldcs(&element_mars[lane]));
    }
}

extern "C" void kernel_launch(void* const* d_in, const int* in_sizes, int n_in,
                              void* d_out, int out_size)
{
    const float4* node_mars    = (const float4*)d_in[0];
    const float4* element_mars = (const float4*)d_in[1];
    const int*    nids         = (const int*)d_in[2];
    const int4*   cids         = (const int4*)d_in[3];
    float4*       out          = (float4*)d_out;

    const int n_prod  = in_sizes[2];          // 500000
    const int n_warps = n_prod + 1;           // +1 warp for the reserved row 0
    const int threads = 256;                  // 8 warps per block
    const int blocks  = (n_warps * 32 + threads - 1) / threads;

    prodlayer_kernel<<<blocks, threads>>>(node_mars, element_mars, nids, cids,
                                          out, n_prod);
}

// round 17
// speedup vs baseline: 1.0042x; 1.0042x over previous
#include <cuda_runtime.h>
#include <cstddef>

// ProdLayer forward: element_mars[nids] = node_mars[cids].sum(axis=1)
//   d_in[0] node_mars     float32  [N_SRC, 128]
//   d_in[1] element_mars  float32  [N_PROD+1, 128]
//   d_in[2] nids          int32    [N_PROD]
//   d_in[3] cids          int32    [N_PROD, 4]
// Output: float32 [N_PROD+1, 128]
//
// FINAL — converged after 16 rounds; design space fully enumerated.
// Flat launch, warp-per-product, float4 lanes: lane l covers float4
// column l of each 512 B row; the 4 child-row gathers are independent,
// perfectly coalesced LDG.128s. __ldcs index reads + __stcs streaming
// output stores (the single measurable policy win, ~-2%; __stwt tested
// and no better).
//
// Roofline argument:
//   traffic irreducibly ~1.13 GB =
//     443 MB compulsory gather reads (≈864K distinct rows x 512 B)
//   + ~420 MB re-reference misses (L2 hit rate pinned at the 126MB/512MB
//     capacity ratio — statistical limit for a uniform-random gather;
//     no reorder beats it without >1 GB of accumulator RMW traffic)
//   + 256 MB streaming writes + ~10 MB indices,
//   sustained at 6.8-6.9 TB/s = 86% of spec HBM — the practical ceiling
//   for this 77/23 random-gather/streaming-store mix on GB300.
// Falsified R3-R16: column tiling (sector-tag amplification), evict_last
// policies, L1 bypass, LDG.256, write-through stores, persistent grids at
// 47% and 92% occupancy (flat CTA replacement pipelines load issue for
// free; grid-stride loops serialize it), MLP 4 vs 8, CTA 128 vs 256,
// index-load reordering.

static constexpr int B_F4 = 32;  // 128 floats / 4 per row

__global__ void __launch_bounds__(256) prodlayer_kernel(
    const float4* __restrict__ node_mars,
    const float4* __restrict__ element_mars,
    const int*    __restrict__ nids,
    const int4*   __restrict__ cids,
    float4*       __restrict__ out,
    int n_prod)
{
    const int gwarp = (int)((blockIdx.x * (unsigned)blockDim.x + threadIdx.x) >> 5);
    const int lane  = threadIdx.x & 31;

    if (gwarp < n_prod) {
        const int4 c = __ldcs(&cids[gwarp]);      // streaming index read

        const float4 a = __ldg(&node_mars[(size_t)c.x * B_F4 + lane]);
        const float4 b = __ldg(&node_mars[(size_t)c.y * B_F4 + lane]);
        const float4 d = __ldg(&node_mars[(size_t)c.z * B_F4 + lane]);
        const float4 e = __ldg(&node_mars[(size_t)c.w * B_F4 + lane]);

        float4 s;
        s.x = (a.x + b.x) + (d.x + e.x);
        s.y = (a.y + b.y) + (d.y + e.y);
        s.z = (a.z + b.z) + (d.z + e.z);
        s.w = (a.w + b.w) + (d.w + e.w);

        const int o = __ldcs(&nids[gwarp]);
        __stcs(&out[(size_t)o * B_F4 + lane], s);  // evict-first streaming store
    } else if (gwarp == n_prod) {
        // Reserved row 0: out row 0 = element_mars row 0 (d_out is poisoned
        // to 0xAA before timing, so row 0 must be written explicitly).
        __stcs(&out[lane], __ldcs(&element_mars[lane]));
    }
}

extern "C" void kernel_launch(void* const* d_in, const int* in_sizes, int n_in,
                              void* d_out, int out_size)
{
    const float4* node_mars    = (const float4*)d_in[0];
    const float4* element_mars = (const float4*)d_in[1];
    const int*    nids         = (const int*)d_in[2];
    const int4*   cids         = (const int4*)d_in[3];
    float4*       out          = (float4*)d_out;

    const int n_prod  = in_sizes[2];          // 500000
    const int n_warps = n_prod + 1;           // +1 warp for the reserved row 0
    const int threads = 256;                  // 8 warps per block
    const int blocks  = (n_warps * 32 + threads - 1) / threads;

    prodlayer_kernel<<<blocks, threads>>>(node_mars, element_mars, nids, cids,
                                          out, n_prod);
}